// round 16
// baseline (speedup 1.0000x reference)
#include <cuda_runtime.h>
#include <cuda_bf16.h>

#define D          128
#define B_MAX      8192
#define CACHE_ROWS 128          // 128 rows * 256B (bf16) = 32 KB dyn -> 5 CTA/SM
#define TPB        256
#define NWARP      (TPB / 32)
#define GS         32           // segments per GEMM block

// Scratch (no allocations allowed): pooled means + segment boundaries
__device__ float g_pooled[B_MAX * D];
__device__ int   g_seg_start[B_MAX + 1];

// ---------------------------------------------------------------------------
// Kernel 1: segment boundaries via transition scan (batch is sorted).
// 16 elements per thread (4 staged int4 loads -> MLP=4).
// ---------------------------------------------------------------------------
__global__ void seg_scan_kernel(const int* __restrict__ batch, int N, int B) {
    int t = blockIdx.x * blockDim.x + threadIdx.x;
    int base = t * 16;
    const bool active = (base < N);
    const bool full   = (base + 16 <= N);

    int4 v0 = make_int4(0,0,0,0), v1 = v0, v2 = v0, v3 = v0;
    if (full) {
        const int4* b4 = (const int4*)batch;
        v0 = b4[t * 4 + 0];
        v1 = b4[t * 4 + 1];
        v2 = b4[t * 4 + 2];
        v3 = b4[t * 4 + 3];
    }

    // previous element from lower lane's last value (lane 0: scalar load)
    int prev = __shfl_up_sync(0xffffffffu, v3.w, 1);
    if ((threadIdx.x & 31) == 0 && active && base > 0)
        prev = batch[base - 1];
    if (base == 0) prev = -1;

    if (!active) return;

    if (full) {
        int vals[16] = {v0.x, v0.y, v0.z, v0.w, v1.x, v1.y, v1.z, v1.w,
                        v2.x, v2.y, v2.z, v2.w, v3.x, v3.y, v3.z, v3.w};
        #pragma unroll
        for (int u = 0; u < 16; u++) {
            int cur = vals[u];
            for (int b = prev + 1; b <= cur; b++) g_seg_start[b] = base + u;
            prev = cur;
        }
        if (base + 16 == N)
            for (int b = prev + 1; b <= B; b++) g_seg_start[b] = N;
    } else {
        prev = (base > 0) ? batch[base - 1] : -1;
        for (int i = base; i < N; i++) {
            int cur = batch[i];
            for (int b = prev + 1; b <= cur; b++) g_seg_start[b] = i;
            if (i == N - 1)
                for (int b = cur + 1; b <= B; b++) g_seg_start[b] = N;
            prev = cur;
        }
    }
}

// ---------------------------------------------------------------------------
// Kernel 2: one CTA per segment, 5 CTAs/SM. bf16-compressed SMEM row cache
// (128 rows in 32 KB) halves the LTS tail re-read traffic.
//  Pass A: stream rows fp32 (6-deep staging); acc in fp32; store bf16 pairs.
//  Pass B: tail (fp32 from L2) first, then cached bf16 rows.
// ---------------------------------------------------------------------------
__global__ __launch_bounds__(TPB, 5)
void pool_kernel(const float* __restrict__ x) {
    extern __shared__ uint2 cacheb[];              // [CACHE_ROWS][32] bf16x4
    __shared__ float4 red[NWARP][32];

    const int seg   = blockIdx.x;
    const int start = g_seg_start[seg];
    const int end   = g_seg_start[seg + 1];
    const int n     = end - start;
    const float inv_n = 1.0f / (float)(n > 0 ? n : 1);
    const int cend  = (start + CACHE_ROWS < end) ? (start + CACHE_ROWS) : end;

    const int tid  = threadIdx.x;
    const int wid  = tid >> 5;
    const int lane = tid & 31;
    const float4* __restrict__ x4 = (const float4*)x;

    // ---- Pass A: segment sum (fp32) + bf16 SMEM cache, 6-deep staging ----
    float4 acc = make_float4(0.f, 0.f, 0.f, 0.f);
    {
        const int U = 6;
        int r = start + wid;
        while (r + (U - 1) * NWARP < end) {
            float4 v[U];
            #pragma unroll
            for (int u = 0; u < U; u++)
                v[u] = x4[(size_t)(r + u * NWARP) * 32 + lane];
            #pragma unroll
            for (int u = 0; u < U; u++) {
                int cr = r + u * NWARP - start;
                if (cr < CACHE_ROWS) {
                    __nv_bfloat162 h0 = __floats2bfloat162_rn(v[u].x, v[u].y);
                    __nv_bfloat162 h1 = __floats2bfloat162_rn(v[u].z, v[u].w);
                    uint2 pk;
                    pk.x = *reinterpret_cast<unsigned*>(&h0);
                    pk.y = *reinterpret_cast<unsigned*>(&h1);
                    cacheb[cr * 32 + lane] = pk;
                }
                acc.x += v[u].x; acc.y += v[u].y; acc.z += v[u].z; acc.w += v[u].w;
            }
            r += U * NWARP;
        }
        for (; r < end; r += NWARP) {
            float4 v = x4[(size_t)r * 32 + lane];
            int cr = r - start;
            if (cr < CACHE_ROWS) {
                __nv_bfloat162 h0 = __floats2bfloat162_rn(v.x, v.y);
                __nv_bfloat162 h1 = __floats2bfloat162_rn(v.z, v.w);
                uint2 pk;
                pk.x = *reinterpret_cast<unsigned*>(&h0);
                pk.y = *reinterpret_cast<unsigned*>(&h1);
                cacheb[cr * 32 + lane] = pk;
            }
            acc.x += v.x; acc.y += v.y; acc.z += v.z; acc.w += v.w;
        }
    }
    red[wid][lane] = acc;
    __syncthreads();

    // Redundant per-thread coarse reduction (no single-warp serialization)
    float4 c;
    {
        float4 s = red[0][lane];
        #pragma unroll
        for (int w = 1; w < NWARP; w++) {
            float4 t = red[w][lane];
            s.x += t.x; s.y += t.y; s.z += t.z; s.w += t.w;
        }
        c.x = s.x * inv_n; c.y = s.y * inv_n; c.z = s.z * inv_n; c.w = s.w * inv_n;
    }
    __syncthreads();   // red[] reused by pass-B reduction

    // ---- Pass B ----
    float4 pacc = make_float4(0.f, 0.f, 0.f, 0.f);

    // (1) uncached tail rows: fp32 loads, L2 hits (touched in pass A)
    {
        const int U = 6;
        int r = cend + wid;
        while (r + (U - 1) * NWARP < end) {
            float4 v[U];
            float  p[U];
            #pragma unroll
            for (int u = 0; u < U; u++)
                v[u] = x4[(size_t)(r + u * NWARP) * 32 + lane];
            #pragma unroll
            for (int u = 0; u < U; u++)
                p[u] = v[u].x * c.x + v[u].y * c.y + v[u].z * c.z + v[u].w * c.w;
            #pragma unroll
            for (int o = 16; o; o >>= 1) {
                #pragma unroll
                for (int u = 0; u < U; u++)
                    p[u] += __shfl_xor_sync(0xffffffffu, p[u], o);
            }
            #pragma unroll
            for (int u = 0; u < U; u++) {
                pacc.x += p[u] * v[u].x; pacc.y += p[u] * v[u].y;
                pacc.z += p[u] * v[u].z; pacc.w += p[u] * v[u].w;
            }
            r += U * NWARP;
        }
        for (; r < end; r += NWARP) {
            float4 v = x4[(size_t)r * 32 + lane];
            float p = v.x * c.x + v.y * c.y + v.z * c.z + v.w * c.w;
            #pragma unroll
            for (int o = 16; o; o >>= 1)
                p += __shfl_xor_sync(0xffffffffu, p, o);
            pacc.x += p * v.x; pacc.y += p * v.y; pacc.z += p * v.z; pacc.w += p * v.w;
        }
    }

    // (2) cached rows from bf16 SMEM
    {
        const int U = 4;
        int r = start + wid;
        while (r + (U - 1) * NWARP < cend) {
            float4 v[U];
            float  p[U];
            #pragma unroll
            for (int u = 0; u < U; u++) {
                uint2 pk = cacheb[(r + u * NWARP - start) * 32 + lane];
                float2 f0 = __bfloat1622float2(*reinterpret_cast<__nv_bfloat162*>(&pk.x));
                float2 f1 = __bfloat1622float2(*reinterpret_cast<__nv_bfloat162*>(&pk.y));
                v[u] = make_float4(f0.x, f0.y, f1.x, f1.y);
            }
            #pragma unroll
            for (int u = 0; u < U; u++)
                p[u] = v[u].x * c.x + v[u].y * c.y + v[u].z * c.z + v[u].w * c.w;
            #pragma unroll
            for (int o = 16; o; o >>= 1) {
                #pragma unroll
                for (int u = 0; u < U; u++)
                    p[u] += __shfl_xor_sync(0xffffffffu, p[u], o);
            }
            #pragma unroll
            for (int u = 0; u < U; u++) {
                pacc.x += p[u] * v[u].x; pacc.y += p[u] * v[u].y;
                pacc.z += p[u] * v[u].z; pacc.w += p[u] * v[u].w;
            }
            r += U * NWARP;
        }
        for (; r < cend; r += NWARP) {
            uint2 pk = cacheb[(r - start) * 32 + lane];
            float2 f0 = __bfloat1622float2(*reinterpret_cast<__nv_bfloat162*>(&pk.x));
            float2 f1 = __bfloat1622float2(*reinterpret_cast<__nv_bfloat162*>(&pk.y));
            float4 v = make_float4(f0.x, f0.y, f1.x, f1.y);
            float p = v.x * c.x + v.y * c.y + v.z * c.z + v.w * c.w;
            #pragma unroll
            for (int o = 16; o; o >>= 1)
                p += __shfl_xor_sync(0xffffffffu, p, o);
            pacc.x += p * v.x; pacc.y += p * v.y; pacc.z += p * v.z; pacc.w += p * v.w;
        }
    }

    red[wid][lane] = pacc;
    __syncthreads();

    if (wid == 0) {
        float4 s = red[0][lane];
        #pragma unroll
        for (int w = 1; w < NWARP; w++) {
            float4 t = red[w][lane];
            s.x += t.x; s.y += t.y; s.z += t.z; s.w += t.w;
        }
        s.x *= inv_n; s.y *= inv_n; s.z *= inv_n; s.w *= inv_n;
        ((float4*)g_pooled)[(size_t)seg * 32 + lane] = s;
    }
}

// ---------------------------------------------------------------------------
// Kernel 3: out = pooled @ W^T + b    ([B,128] x [128,128])
// ---------------------------------------------------------------------------
__global__ __launch_bounds__(256)
void gemm_kernel(const float* __restrict__ W, const float* __restrict__ bias,
                 float* __restrict__ out, int B) {
    extern __shared__ float sm[];
    float* Wt = sm;                 // [128][132]
    float* ps = sm + 128 * 132;     // [GS][128]

    const int t  = threadIdx.x;
    const int s0 = blockIdx.x * GS;

    for (int idx = t; idx < D * D; idx += 256) {
        int o = idx >> 7, k = idx & 127;
        Wt[k * 132 + o] = W[idx];
    }
    {
        float4* ps4 = (float4*)ps;
        const float4* gp4 = (const float4*)(g_pooled + (size_t)s0 * D);
        int nvec = GS * D / 4;
        for (int idx = t; idx < nvec; idx += 256) {
            int row = s0 + (idx >> 5);
            ps4[idx] = (row < B) ? gp4[idx] : make_float4(0.f, 0.f, 0.f, 0.f);
        }
    }
    __syncthreads();

    const int o4 = (t & 31) * 4;
    const int sb = (t >> 5) * 4;

    float acc[4][4];
    #pragma unroll
    for (int j = 0; j < 4; j++)
        #pragma unroll
        for (int i = 0; i < 4; i++) acc[j][i] = 0.f;

    #pragma unroll 4
    for (int k = 0; k < D; k++) {
        float4 w4 = *(const float4*)&Wt[k * 132 + o4];
        #pragma unroll
        for (int j = 0; j < 4; j++) {
            float pv = ps[(sb + j) * D + k];
            acc[j][0] += pv * w4.x;
            acc[j][1] += pv * w4.y;
            acc[j][2] += pv * w4.z;
            acc[j][3] += pv * w4.w;
        }
    }

    float4 bb = *(const float4*)&bias[o4];
    #pragma unroll
    for (int j = 0; j < 4; j++) {
        int s = s0 + sb + j;
        if (s < B) {
            float4 r = make_float4(acc[j][0] + bb.x, acc[j][1] + bb.y,
                                   acc[j][2] + bb.z, acc[j][3] + bb.w);
            *(float4*)&out[(size_t)s * D + o4] = r;
        }
    }
}

// ---------------------------------------------------------------------------
extern "C" void kernel_launch(void* const* d_in, const int* in_sizes, int n_in,
                              void* d_out, int out_size) {
    const float* x     = (const float*)d_in[0];
    const int*   batch = (const int*)d_in[1];
    const float* W     = (const float*)d_in[2];
    const float* bias  = (const float*)d_in[3];
    (void)n_in;

    const int N = in_sizes[1];
    const int B = out_size / D;

    const size_t pool_smem = (size_t)CACHE_ROWS * 32 * sizeof(uint2);    // 32 KB
    const size_t gemm_smem = (size_t)(128 * 132 + GS * D) * sizeof(float);

    cudaFuncSetAttribute(pool_kernel, cudaFuncAttributeMaxDynamicSharedMemorySize,
                         (int)pool_smem);
    cudaFuncSetAttribute(gemm_kernel, cudaFuncAttributeMaxDynamicSharedMemorySize,
                         (int)gemm_smem);

    int nthreads16 = (N + 15) / 16;
    seg_scan_kernel<<<(nthreads16 + 255) / 256, 256>>>(batch, N, B);
    pool_kernel<<<B, TPB, pool_smem>>>(x);
    gemm_kernel<<<(B + GS - 1) / GS, 256, gemm_smem>>>(W, bias, (float*)d_out, B);
}

// round 17
// speedup vs baseline: 1.0237x; 1.0237x over previous
#include <cuda_runtime.h>
#include <cuda_bf16.h>

#define D          128
#define B_MAX      8192
#define CACHE_ROWS 64           // 64 rows * 512B = 32 KB dynamic smem -> 5 CTA/SM
#define TPB        256
#define NWARP      (TPB / 32)
#define GS         32           // segments per GEMM block

// Scratch (no allocations allowed): pooled means + segment boundaries
__device__ float g_pooled[B_MAX * D];
__device__ int   g_seg_start[B_MAX + 1];

// ---------------------------------------------------------------------------
// Kernel 1: segment boundaries via transition scan (batch is sorted), int4,
// previous-element via shfl (only lane 0 issues the extra scalar load).
// ---------------------------------------------------------------------------
__global__ void seg_scan_kernel(const int* __restrict__ batch, int N, int B) {
    int i4 = blockIdx.x * blockDim.x + threadIdx.x;
    int base = i4 * 4;
    const bool active = (base < N);

    int4 v = make_int4(0, 0, 0, 0);
    if (active) {
        if (base + 3 < N) {
            v = ((const int4*)batch)[i4];
        } else {
            v.x = batch[base];
            v.y = (base + 1 < N) ? batch[base + 1] : v.x;
            v.z = (base + 2 < N) ? batch[base + 2] : v.y;
            v.w = (base + 3 < N) ? batch[base + 3] : v.z;
        }
    }

    // previous element (batch[base-1]) from the lower lane's v.w
    int prev = __shfl_up_sync(0xffffffffu, v.w, 1);
    if ((threadIdx.x & 31) == 0 && active && base > 0)
        prev = batch[base - 1];
    if (base == 0) prev = -1;

    if (!active) return;

    int vals[4] = {v.x, v.y, v.z, v.w};
    #pragma unroll
    for (int u = 0; u < 4; u++) {
        int idx = base + u;
        if (idx < N) {
            int cur = vals[u];
            for (int b = prev + 1; b <= cur; b++) g_seg_start[b] = idx;
            if (idx == N - 1)
                for (int b = cur + 1; b <= B; b++) g_seg_start[b] = N;
            prev = cur;
        }
    }
}

// ---------------------------------------------------------------------------
// Kernel 2: one CTA per segment, 5 CTAs/SM (measured optimum, R14 config).
//  Pass A: stream rows (6-deep staging), cache first CACHE_ROWS in SMEM,
//          accumulate segment sum; coarse mean computed redundantly by every
//          thread (one barrier, no single-warp serialization).
//  Pass B: tail (uncached, recent L2 hit) rows first, then cached rows.
//  Epilogue: 128-thread parallel scalar reduction (no single-warp tail).
// ---------------------------------------------------------------------------
__global__ __launch_bounds__(TPB, 5)
void pool_kernel(const float* __restrict__ x) {
    extern __shared__ float4 cache[];              // [CACHE_ROWS][32]
    __shared__ float4 red[NWARP][32];

    const int seg   = blockIdx.x;
    const int start = g_seg_start[seg];
    const int end   = g_seg_start[seg + 1];
    const int n     = end - start;
    const float inv_n = 1.0f / (float)(n > 0 ? n : 1);
    const int cend  = (start + CACHE_ROWS < end) ? (start + CACHE_ROWS) : end;

    const int tid  = threadIdx.x;
    const int wid  = tid >> 5;
    const int lane = tid & 31;
    const float4* __restrict__ x4 = (const float4*)x;

    // ---- Pass A: segment sum + SMEM cache, 6-deep load staging ----
    float4 acc = make_float4(0.f, 0.f, 0.f, 0.f);
    {
        const int U = 6;
        int r = start + wid;
        while (r + (U - 1) * NWARP < end) {
            float4 v[U];
            #pragma unroll
            for (int u = 0; u < U; u++)
                v[u] = x4[(size_t)(r + u * NWARP) * 32 + lane];
            #pragma unroll
            for (int u = 0; u < U; u++) {
                int cr = r + u * NWARP - start;
                if (cr < CACHE_ROWS) cache[cr * 32 + lane] = v[u];
                acc.x += v[u].x; acc.y += v[u].y; acc.z += v[u].z; acc.w += v[u].w;
            }
            r += U * NWARP;
        }
        for (; r < end; r += NWARP) {
            float4 v = x4[(size_t)r * 32 + lane];
            int cr = r - start;
            if (cr < CACHE_ROWS) cache[cr * 32 + lane] = v;
            acc.x += v.x; acc.y += v.y; acc.z += v.z; acc.w += v.w;
        }
    }
    red[wid][lane] = acc;
    __syncthreads();

    // Redundant per-thread coarse reduction: every thread sums the 8 warp
    // partials for its lane (broadcast LDS, conflict-free) -> c in registers.
    float4 c;
    {
        float4 s = red[0][lane];
        #pragma unroll
        for (int w = 1; w < NWARP; w++) {
            float4 t = red[w][lane];
            s.x += t.x; s.y += t.y; s.z += t.z; s.w += t.w;
        }
        c.x = s.x * inv_n; c.y = s.y * inv_n; c.z = s.z * inv_n; c.w = s.w * inv_n;
    }
    __syncthreads();   // red[] will be reused by pass-B reduction

    // ---- Pass B ----
    float4 pacc = make_float4(0.f, 0.f, 0.f, 0.f);

    // (1) uncached tail rows: loads land as L2 hits (lines touched in pass A)
    {
        const int U = 6;
        int r = cend + wid;
        while (r + (U - 1) * NWARP < end) {
            float4 v[U];
            float  p[U];
            #pragma unroll
            for (int u = 0; u < U; u++)
                v[u] = x4[(size_t)(r + u * NWARP) * 32 + lane];
            #pragma unroll
            for (int u = 0; u < U; u++)
                p[u] = v[u].x * c.x + v[u].y * c.y + v[u].z * c.z + v[u].w * c.w;
            #pragma unroll
            for (int o = 16; o; o >>= 1) {
                #pragma unroll
                for (int u = 0; u < U; u++)
                    p[u] += __shfl_xor_sync(0xffffffffu, p[u], o);
            }
            #pragma unroll
            for (int u = 0; u < U; u++) {
                pacc.x += p[u] * v[u].x; pacc.y += p[u] * v[u].y;
                pacc.z += p[u] * v[u].z; pacc.w += p[u] * v[u].w;
            }
            r += U * NWARP;
        }
        for (; r < end; r += NWARP) {
            float4 v = x4[(size_t)r * 32 + lane];
            float p = v.x * c.x + v.y * c.y + v.z * c.z + v.w * c.w;
            #pragma unroll
            for (int o = 16; o; o >>= 1)
                p += __shfl_xor_sync(0xffffffffu, p, o);
            pacc.x += p * v.x; pacc.y += p * v.y; pacc.z += p * v.z; pacc.w += p * v.w;
        }
    }

    // (2) cached rows from SMEM
    {
        const int U = 4;
        int r = start + wid;
        while (r + (U - 1) * NWARP < cend) {
            float4 v[U];
            float  p[U];
            #pragma unroll
            for (int u = 0; u < U; u++)
                v[u] = cache[(r + u * NWARP - start) * 32 + lane];
            #pragma unroll
            for (int u = 0; u < U; u++)
                p[u] = v[u].x * c.x + v[u].y * c.y + v[u].z * c.z + v[u].w * c.w;
            #pragma unroll
            for (int o = 16; o; o >>= 1) {
                #pragma unroll
                for (int u = 0; u < U; u++)
                    p[u] += __shfl_xor_sync(0xffffffffu, p[u], o);
            }
            #pragma unroll
            for (int u = 0; u < U; u++) {
                pacc.x += p[u] * v[u].x; pacc.y += p[u] * v[u].y;
                pacc.z += p[u] * v[u].z; pacc.w += p[u] * v[u].w;
            }
            r += U * NWARP;
        }
        for (; r < cend; r += NWARP) {
            float4 v = cache[(r - start) * 32 + lane];
            float p = v.x * c.x + v.y * c.y + v.z * c.z + v.w * c.w;
            #pragma unroll
            for (int o = 16; o; o >>= 1)
                p += __shfl_xor_sync(0xffffffffu, p, o);
            pacc.x += p * v.x; pacc.y += p * v.y; pacc.z += p * v.z; pacc.w += p * v.w;
        }
    }

    red[wid][lane] = pacc;
    __syncthreads();

    // Parallel epilogue: 128 threads, one output float each.
    // lane2 = tid>>2, comp = tid&3 -> conflict-free LDS, coalesced STG.
    if (tid < 128) {
        const float* redf = (const float*)red;     // [8][32][4] floats
        const int lane2 = tid >> 2;
        const int comp  = tid & 3;
        float s = 0.f;
        #pragma unroll
        for (int w = 0; w < NWARP; w++)
            s += redf[w * 128 + lane2 * 4 + comp];
        g_pooled[(size_t)seg * D + lane2 * 4 + comp] = s * inv_n;
    }
}

// ---------------------------------------------------------------------------
// Kernel 3: out = pooled @ W^T + b    ([B,128] x [128,128])
// ---------------------------------------------------------------------------
__global__ __launch_bounds__(256)
void gemm_kernel(const float* __restrict__ W, const float* __restrict__ bias,
                 float* __restrict__ out, int B) {
    extern __shared__ float sm[];
    float* Wt = sm;                 // [128][132]
    float* ps = sm + 128 * 132;     // [GS][128]

    const int t  = threadIdx.x;
    const int s0 = blockIdx.x * GS;

    for (int idx = t; idx < D * D; idx += 256) {
        int o = idx >> 7, k = idx & 127;
        Wt[k * 132 + o] = W[idx];
    }
    {
        float4* ps4 = (float4*)ps;
        const float4* gp4 = (const float4*)(g_pooled + (size_t)s0 * D);
        int nvec = GS * D / 4;
        for (int idx = t; idx < nvec; idx += 256) {
            int row = s0 + (idx >> 5);
            ps4[idx] = (row < B) ? gp4[idx] : make_float4(0.f, 0.f, 0.f, 0.f);
        }
    }
    __syncthreads();

    const int o4 = (t & 31) * 4;
    const int sb = (t >> 5) * 4;

    float acc[4][4];
    #pragma unroll
    for (int j = 0; j < 4; j++)
        #pragma unroll
        for (int i = 0; i < 4; i++) acc[j][i] = 0.f;

    #pragma unroll 4
    for (int k = 0; k < D; k++) {
        float4 w4 = *(const float4*)&Wt[k * 132 + o4];
        #pragma unroll
        for (int j = 0; j < 4; j++) {
            float pv = ps[(sb + j) * D + k];
            acc[j][0] += pv * w4.x;
            acc[j][1] += pv * w4.y;
            acc[j][2] += pv * w4.z;
            acc[j][3] += pv * w4.w;
        }
    }

    float4 bb = *(const float4*)&bias[o4];
    #pragma unroll
    for (int j = 0; j < 4; j++) {
        int s = s0 + sb + j;
        if (s < B) {
            float4 r = make_float4(acc[j][0] + bb.x, acc[j][1] + bb.y,
                                   acc[j][2] + bb.z, acc[j][3] + bb.w);
            *(float4*)&out[(size_t)s * D + o4] = r;
        }
    }
}

// ---------------------------------------------------------------------------
extern "C" void kernel_launch(void* const* d_in, const int* in_sizes, int n_in,
                              void* d_out, int out_size) {
    const float* x     = (const float*)d_in[0];
    const int*   batch = (const int*)d_in[1];
    const float* W     = (const float*)d_in[2];
    const float* bias  = (const float*)d_in[3];
    (void)n_in;

    const int N = in_sizes[1];
    const int B = out_size / D;

    const size_t pool_smem = (size_t)CACHE_ROWS * 32 * sizeof(float4);   // 32 KB
    const size_t gemm_smem = (size_t)(128 * 132 + GS * D) * sizeof(float);

    cudaFuncSetAttribute(pool_kernel, cudaFuncAttributeMaxDynamicSharedMemorySize,
                         (int)pool_smem);
    cudaFuncSetAttribute(gemm_kernel, cudaFuncAttributeMaxDynamicSharedMemorySize,
                         (int)gemm_smem);

    int nvec4 = (N + 3) / 4;
    seg_scan_kernel<<<(nvec4 + 255) / 256, 256>>>(batch, N, B);
    pool_kernel<<<B, TPB, pool_smem>>>(x);
    gemm_kernel<<<(B + GS - 1) / GS, 256, gemm_smem>>>(W, bias, (float*)d_out, B);
}